// round 8
// baseline (speedup 1.0000x reference)
#include <cuda_runtime.h>

// Problem shape (fixed by setup_inputs):
//   x1: [B=32, C=64, h=42, w=42]       float32
//   x2: [B=32, S=25, C=64, h=42, w=42] float32
//   out: [B, S*h*w] = [32, 44100]      float32
// out[b, s*HW + p] = sqrt( sum_c (x1[b,c,p] - x2[b,s,c,p])^2 )
//
// R4 champion structure: 1 thread = 4 pixels of one (b,s), double-buffered
// 4-channel register pipeline (8 float4 loads in flight per thread, always).
// x2 -> __ldcg (L2-only, zero reuse), x1 -> caching load (L1+L2 reuse),
// out -> __stcs (evict-first).

#define B_  32
#define S_  25
#define C_  64
#define HW_ 1764          // 42*42
#define HW4_ 441          // HW/4 (exact)
#define TOTAL_ (B_ * S_ * HW4_)   // 352800 threads, one float4 output each

#define CB_ 4                      // channels per pipeline stage
#define NSTAGE_ (C_ / CB_)         // 16 stages

__global__ __launch_bounds__(256, 3)
void euclidean_block_kernel(const float* __restrict__ x1,
                            const float* __restrict__ x2,
                            float* __restrict__ out) {
    int t = blockIdx.x * blockDim.x + threadIdx.x;
    if (t >= TOTAL_) return;

    int p4 = t % HW4_;          // which float4 within the 1764-pixel plane
    int bs = t / HW4_;          // (b*S + s)
    int b  = bs / S_;

    const float4* __restrict__ x1p =
        reinterpret_cast<const float4*>(x1 + (size_t)b * C_ * HW_) + p4;
    const float4* __restrict__ x2p =
        reinterpret_cast<const float4*>(x2 + (size_t)bs * C_ * HW_) + p4;

    float ax = 0.f, ay = 0.f, az = 0.f, aw = 0.f;

    // Double-buffered register pipeline: while consuming stage s, stage s+1's
    // 8 loads are already in flight.
    float4 a[2][CB_], v[2][CB_];

    // Prologue: stage 0 -> buffer 0.
    #pragma unroll
    for (int i = 0; i < CB_; ++i) {
        a[0][i] = x1p[i * HW4_];                 // caching load (L1+L2)
        v[0][i] = __ldcg(&x2p[i * HW4_]);        // L2-only, no L1 alloc
    }

    #pragma unroll
    for (int s = 0; s < NSTAGE_; ++s) {
        const int cur = s & 1;
        const int nxt = cur ^ 1;

        if (s + 1 < NSTAGE_) {
            const int c0 = (s + 1) * CB_;
            #pragma unroll
            for (int i = 0; i < CB_; ++i) {
                a[nxt][i] = x1p[(c0 + i) * HW4_];
                v[nxt][i] = __ldcg(&x2p[(c0 + i) * HW4_]);
            }
        }

        #pragma unroll
        for (int i = 0; i < CB_; ++i) {
            float d0 = a[cur][i].x - v[cur][i].x;
            float d1 = a[cur][i].y - v[cur][i].y;
            float d2 = a[cur][i].z - v[cur][i].z;
            float d3 = a[cur][i].w - v[cur][i].w;
            ax = fmaf(d0, d0, ax);
            ay = fmaf(d1, d1, ay);
            az = fmaf(d2, d2, az);
            aw = fmaf(d3, d3, aw);
        }
    }

    float4 r;
    r.x = sqrtf(ax);
    r.y = sqrtf(ay);
    r.z = sqrtf(az);
    r.w = sqrtf(aw);

    __stcs(&reinterpret_cast<float4*>(out)[(size_t)bs * HW4_ + p4], r);
}

extern "C" void kernel_launch(void* const* d_in, const int* in_sizes, int n_in,
                              void* d_out, int out_size) {
    const float* x1 = (const float*)d_in[0];
    const float* x2 = (const float*)d_in[1];
    float* out = (float*)d_out;

    const int threads = 256;
    const int blocks = (TOTAL_ + threads - 1) / threads;  // 1379, flat grid
    euclidean_block_kernel<<<blocks, threads>>>(x1, x2, out);
}

// round 9
// speedup vs baseline: 1.0385x; 1.0385x over previous
#include <cuda_runtime.h>

// Problem shape (fixed by setup_inputs):
//   x1: [B=32, C=64, h=42, w=42]       float32
//   x2: [B=32, S=25, C=64, h=42, w=42] float32
//   out: [B, S*h*w] = [32, 44100]      float32
// out[b, s*HW + p] = sqrt( sum_c (x1[b,c,p] - x2[b,s,c,p])^2 )
//
// Final champion (R4 configuration): 1 thread = 4 pixels of one (b,s),
// double-buffered 4-channel register pipeline (8 float4 loads always in
// flight per thread). x2 -> __ldcs (streaming, evict-first), x1 -> caching
// loads (L1/L2 reuse across the 25 supports), plain coalesced float4 stores.
// Measured at ~81.6% DRAM-active / 6.47 TB/s with traffic at the 381 MB
// floor — the achievable HBM roofline for this access mix.

#define B_  32
#define S_  25
#define C_  64
#define HW_ 1764          // 42*42
#define HW4_ 441          // HW/4 (exact)
#define TOTAL_ (B_ * S_ * HW4_)   // 352800 threads, one float4 output each

#define CB_ 4                      // channels per pipeline stage
#define NSTAGE_ (C_ / CB_)         // 16 stages

__global__ __launch_bounds__(256, 3)
void euclidean_block_kernel(const float* __restrict__ x1,
                            const float* __restrict__ x2,
                            float* __restrict__ out) {
    int t = blockIdx.x * blockDim.x + threadIdx.x;
    if (t >= TOTAL_) return;

    int p4 = t % HW4_;          // which float4 within the 1764-pixel plane
    int bs = t / HW4_;          // (b*S + s)
    int b  = bs / S_;

    const float4* __restrict__ x1p =
        reinterpret_cast<const float4*>(x1 + (size_t)b * C_ * HW_) + p4;
    const float4* __restrict__ x2p =
        reinterpret_cast<const float4*>(x2 + (size_t)bs * C_ * HW_) + p4;

    float ax = 0.f, ay = 0.f, az = 0.f, aw = 0.f;

    // Double-buffered register pipeline: while consuming stage s, stage s+1's
    // 8 loads are already in flight -> the per-warp DRAM request stream never
    // drains to zero (vs. the batch-then-drain pattern).
    float4 a[2][CB_], v[2][CB_];

    // Prologue: load stage 0 into buffer 0.
    #pragma unroll
    for (int i = 0; i < CB_; ++i) {
        a[0][i] = x1p[i * HW4_];
        v[0][i] = __ldcs(&x2p[i * HW4_]);
    }

    #pragma unroll
    for (int s = 0; s < NSTAGE_; ++s) {
        const int cur = s & 1;
        const int nxt = cur ^ 1;

        // Prefetch next stage before consuming current one.
        if (s + 1 < NSTAGE_) {
            const int c0 = (s + 1) * CB_;
            #pragma unroll
            for (int i = 0; i < CB_; ++i) {
                a[nxt][i] = x1p[(c0 + i) * HW4_];
                v[nxt][i] = __ldcs(&x2p[(c0 + i) * HW4_]);
            }
        }

        // Consume current stage.
        #pragma unroll
        for (int i = 0; i < CB_; ++i) {
            float d0 = a[cur][i].x - v[cur][i].x;
            float d1 = a[cur][i].y - v[cur][i].y;
            float d2 = a[cur][i].z - v[cur][i].z;
            float d3 = a[cur][i].w - v[cur][i].w;
            ax = fmaf(d0, d0, ax);
            ay = fmaf(d1, d1, ay);
            az = fmaf(d2, d2, az);
            aw = fmaf(d3, d3, aw);
        }
    }

    float4 r;
    r.x = sqrtf(ax);
    r.y = sqrtf(ay);
    r.z = sqrtf(az);
    r.w = sqrtf(aw);

    reinterpret_cast<float4*>(out)[(size_t)bs * HW4_ + p4] = r;
}

extern "C" void kernel_launch(void* const* d_in, const int* in_sizes, int n_in,
                              void* d_out, int out_size) {
    const float* x1 = (const float*)d_in[0];
    const float* x2 = (const float*)d_in[1];
    float* out = (float*)d_out;

    const int threads = 256;
    const int blocks = (TOTAL_ + threads - 1) / threads;  // 1379, flat grid
    euclidean_block_kernel<<<blocks, threads>>>(x1, x2, out);
}

// round 10
// speedup vs baseline: 1.0782x; 1.0383x over previous
#include <cuda_runtime.h>

// Problem shape (fixed by setup_inputs):
//   x1: [B=32, C=64, h=42, w=42]       float32
//   x2: [B=32, S=25, C=64, h=42, w=42] float32
//   out: [B, S*h*w] = [32, 44100]      float32
// out[b, s*HW + p] = sqrt( sum_c (x1[b,c,p] - x2[b,s,c,p])^2 )
//
// Triple-buffered register pipeline (prefetch distance 2): each thread keeps
// 16 float4 loads in flight continuously (deep like R2, smooth like R4).
// x2 -> __ldcs streaming; x1 -> caching loads; plain coalesced stores.

#define B_  32
#define S_  25
#define C_  64
#define HW_ 1764          // 42*42
#define HW4_ 441          // HW/4 (exact)
#define TOTAL_ (B_ * S_ * HW4_)   // 352800 threads, one float4 output each

#define CB_ 4                      // channels per pipeline stage
#define NSTAGE_ (C_ / CB_)         // 16 stages
#define NBUF_ 3                    // prefetch distance 2

__global__ __launch_bounds__(256, 2)
void euclidean_block_kernel(const float* __restrict__ x1,
                            const float* __restrict__ x2,
                            float* __restrict__ out) {
    int t = blockIdx.x * blockDim.x + threadIdx.x;
    if (t >= TOTAL_) return;

    int p4 = t % HW4_;          // which float4 within the 1764-pixel plane
    int bs = t / HW4_;          // (b*S + s)
    int b  = bs / S_;

    const float4* __restrict__ x1p =
        reinterpret_cast<const float4*>(x1 + (size_t)b * C_ * HW_) + p4;
    const float4* __restrict__ x2p =
        reinterpret_cast<const float4*>(x2 + (size_t)bs * C_ * HW_) + p4;

    float ax = 0.f, ay = 0.f, az = 0.f, aw = 0.f;

    float4 a[NBUF_][CB_], v[NBUF_][CB_];

    // Prologue: stages 0 and 1 in flight before any consumption.
    #pragma unroll
    for (int s = 0; s < 2; ++s) {
        #pragma unroll
        for (int i = 0; i < CB_; ++i) {
            a[s][i] = x1p[(s * CB_ + i) * HW4_];
            v[s][i] = __ldcs(&x2p[(s * CB_ + i) * HW4_]);
        }
    }

    #pragma unroll
    for (int s = 0; s < NSTAGE_; ++s) {
        const int cur = s % NBUF_;

        // Prefetch stage s+2 -> keeps 16 loads outstanding at all times.
        if (s + 2 < NSTAGE_) {
            const int pf = (s + 2) % NBUF_;
            const int c0 = (s + 2) * CB_;
            #pragma unroll
            for (int i = 0; i < CB_; ++i) {
                a[pf][i] = x1p[(c0 + i) * HW4_];
                v[pf][i] = __ldcs(&x2p[(c0 + i) * HW4_]);
            }
        }

        // Consume stage s.
        #pragma unroll
        for (int i = 0; i < CB_; ++i) {
            float d0 = a[cur][i].x - v[cur][i].x;
            float d1 = a[cur][i].y - v[cur][i].y;
            float d2 = a[cur][i].z - v[cur][i].z;
            float d3 = a[cur][i].w - v[cur][i].w;
            ax = fmaf(d0, d0, ax);
            ay = fmaf(d1, d1, ay);
            az = fmaf(d2, d2, az);
            aw = fmaf(d3, d3, aw);
        }
    }

    float4 r;
    r.x = sqrtf(ax);
    r.y = sqrtf(ay);
    r.z = sqrtf(az);
    r.w = sqrtf(aw);

    reinterpret_cast<float4*>(out)[(size_t)bs * HW4_ + p4] = r;
}

extern "C" void kernel_launch(void* const* d_in, const int* in_sizes, int n_in,
                              void* d_out, int out_size) {
    const float* x1 = (const float*)d_in[0];
    const float* x2 = (const float*)d_in[1];
    float* out = (float*)d_out;

    const int threads = 256;
    const int blocks = (TOTAL_ + threads - 1) / threads;  // 1379, flat grid
    euclidean_block_kernel<<<blocks, threads>>>(x1, x2, out);
}